// round 12
// baseline (speedup 1.0000x reference)
#include <cuda_runtime.h>
#include <cuda_bf16.h>
#include <stdint.h>

// CRF log-likelihood: B=128, S=1024, T=256.
// Linear-domain forward recursion, one CTA per batch, 256 threads, thread=j.
//   q_t,j = (sum_i q_{t-1,i} E_ij) * exp(emit_t,j) / q_{t-1,0}
// E column in registers (128 bf16x2). q stored bf16 in smem (broadcast LDS).
// Split-phase named barrier (R10): bar.arrive after the q store; emit LDG +
// __expf prefetch run in the arrive->wait window; bar.sync just before
// consuming q. The normalizer q_{t-1,0} is extracted from the MAC's OWN
// first chunk load (low bf16 of p4[0].x) -- no extra smem access, divide
// hidden under the MAC. hist[] records q_t,0 for the final CC telescope:
//   logZ = CC - log hist[S-1] + log sum_j q_{S-1,j} exp(end_j)   (exact).

#define CRF_B 128
#define CRF_S 1024
#define CRF_T 256
#define NTH   256
#define BAR_CNT (2 * NTH)

__device__ __forceinline__ void bar_arrive1() {
    asm volatile("bar.arrive 1, %0;" :: "r"(BAR_CNT) : "memory");
}
__device__ __forceinline__ void bar_wait1() {
    asm volatile("bar.sync 1, %0;" :: "r"(BAR_CNT) : "memory");
}
__device__ __forceinline__ __nv_bfloat162 u2b(uint32_t u) {
    return *reinterpret_cast<__nv_bfloat162*>(&u);
}

__device__ __forceinline__ float warp_sum(float v) {
#pragma unroll
    for (int o = 16; o > 0; o >>= 1)
        v += __shfl_xor_sync(0xffffffffu, v, o);
    return v;
}

__global__ void crf_zero(float* out) {
    if (threadIdx.x == 0 && blockIdx.x == 0) out[0] = 0.0f;
}

__global__ void __launch_bounds__(NTH, 1) crf_forward_kernel(
    const float* __restrict__ logits,   // (B, S, T) f32
    const int*   __restrict__ tags,     // (B, S) i32
    const float* __restrict__ trans,    // (T, T) f32
    const float* __restrict__ start_t,  // (T,) f32
    const float* __restrict__ end_t,    // (T,) f32
    float* __restrict__ out)            // scalar
{
    __shared__ __align__(16) __nv_bfloat16 pbuf[2][CRF_T];
    __shared__ __align__(16) float hist[CRF_S];   // q_t,0 history
    __shared__ float red[3][8];

    const int j    = threadIdx.x;
    const int w    = j >> 5;
    const int lane = j & 31;
    const int b    = blockIdx.x;
    const float* lg = logits + (size_t)b * (CRF_S * CRF_T);

    // ---- E column j in registers: ereg[k] = (E[2k][j], E[2k+1][j]) ----
    __nv_bfloat162 ereg[128];
#pragma unroll
    for (int k = 0; k < 128; ++k) {
        float e0 = __expf(trans[(2 * k)     * CRF_T + j]);
        float e1 = __expf(trans[(2 * k + 1) * CRF_T + j]);
        ereg[k] = __floats2bfloat162_rn(e0, e1);
    }
    const float endv = end_t[j];

    // ---- t = 0: q_0 = exp(u_0) ----
    float u = start_t[j] + lg[j];
    float q0 = __expf(u);
    pbuf[0][j] = __float2bfloat16(q0);
    if (j == 0) hist[0] = __bfloat162float(__float2bfloat16(q0));
    __syncthreads();
    bar_arrive1();                        // open phase 0

    // emit pipeline: W_cur = exp(emit_t) ready one step ahead
    float e_raw = lg[(size_t)2 * CRF_T + j];          // emit for t = 2
    float W_cur = __expf(lg[(size_t)1 * CRF_T + j]);  // exp(emit) for t = 1
    __nv_bfloat162 q2 = __float2bfloat162_rn(q0);     // last q (bf16x2)

    // ---- forward scan, steps 1..S-1 ----
#pragma unroll 1
    for (int t = 1; t < CRF_S; ++t) {
        // arrive->wait window: independent prefetch work
        float W_next = __expf(e_raw);
        int tn = (t + 2 < CRF_S) ? (t + 2) : (CRF_S - 1);
        e_raw = lg[(size_t)tn * CRF_T + j];

        bar_wait1();                      // q_{t-1} now visible

        const uint4* p4 = reinterpret_cast<const uint4*>(pbuf[(t - 1) & 1]);
        uint4 pw0 = p4[0];                // chunk 0: q[0..7]
        // normalizer = q_{t-1,0} = low bf16 of pw0.x (same value as hist[t-1])
        float qprev = __bfloat162float(__low2bfloat16(u2b(pw0.x)));
        float Wi = __fdividef(W_cur, qprev);          // hidden under MAC
        __nv_bfloat162 Wi2 = __floats2bfloat162_rn(Wi, Wi);

        __nv_bfloat162 z = __floats2bfloat162_rn(0.f, 0.f);
        __nv_bfloat162 a0 = z, a1 = z, a2 = z, a3 = z;
        __nv_bfloat162 a4 = z, a5 = z, a6 = z, a7 = z;
        // chunk 0 (already loaded)
        a0 = __hfma2(u2b(pw0.x), ereg[0], a0);
        a1 = __hfma2(u2b(pw0.y), ereg[1], a1);
        a2 = __hfma2(u2b(pw0.z), ereg[2], a2);
        a3 = __hfma2(u2b(pw0.w), ereg[3], a3);
#pragma unroll
        for (int c = 1; c < 32; c += 2) {
            uint4 pa = p4[c];
            uint4 pb = p4[c + 1 < 32 ? c + 1 : 0];    // c=31 pairs with dummy
            a4 = __hfma2(u2b(pa.x), ereg[4 * c + 0], a4);
            a5 = __hfma2(u2b(pa.y), ereg[4 * c + 1], a5);
            a6 = __hfma2(u2b(pa.z), ereg[4 * c + 2], a6);
            a7 = __hfma2(u2b(pa.w), ereg[4 * c + 3], a7);
            if (c + 1 < 32) {
                a0 = __hfma2(u2b(pb.x), ereg[4 * c + 4], a0);
                a1 = __hfma2(u2b(pb.y), ereg[4 * c + 5], a1);
                a2 = __hfma2(u2b(pb.z), ereg[4 * c + 6], a2);
                a3 = __hfma2(u2b(pb.w), ereg[4 * c + 7], a3);
            }
        }
        __nv_bfloat162 b0 = __hadd2(a0, a1);
        __nv_bfloat162 b1 = __hadd2(a2, a3);
        __nv_bfloat162 b2 = __hadd2(a4, a5);
        __nv_bfloat162 b3 = __hadd2(a6, a7);
        __nv_bfloat162 s  = __hadd2(__hadd2(b0, b1), __hadd2(b2, b3));
        __nv_bfloat162 tot = __hadd2(s, __lowhigh2highlow(s));
        q2 = __hmul2(tot, Wi2);                       // q_t,j (bf16x2)

        pbuf[t & 1][j] = __low2bfloat16(q2);          // STS.16
        if (j == 0) hist[t] = __bfloat162float(__low2bfloat16(q2));
        bar_arrive1();                                // open next phase

        W_cur = W_next;
    }
    bar_wait1();                                      // close final phase

    // ---- logZ pieces ----
    float qf = __bfloat162float(__low2bfloat16(q2));  // q_{S-1,j}
    // (a) sum_j q_{S-1,j} * exp(end_j)
    float ws = warp_sum(qf * __expf(endv));
    if (lane == 0) red[0][w] = ws;

    // (b) CC = sum_t log hist[t]  (4 entries per thread)
    float cc = __logf(hist[j]) + __logf(hist[j + 256])
             + __logf(hist[j + 512]) + __logf(hist[j + 768]);
    float wcc = warp_sum(cc);
    if (lane == 0) red[2][w] = wcc;

    // (c) joint score (numerator); mask is all-ones for this problem
    const int* tg = tags + b * CRF_S;
    float num = 0.f;
#pragma unroll
    for (int t = j; t < CRF_S; t += NTH) {
        int tt = tg[t];
        num += lg[(size_t)t * CRF_T + tt];
        if (t + 1 < CRF_S) num += trans[tt * CRF_T + tg[t + 1]];
    }
    if (j == 0) num += start_t[tg[0]] + end_t[tg[CRF_S - 1]];
    float wsn = warp_sum(num);
    if (lane == 0) red[1][w] = wsn;
    __syncthreads();

    if (j == 0) {
        float ssum = 0.f, tot = 0.f, CC = 0.f;
#pragma unroll
        for (int k = 0; k < 8; ++k) { ssum += red[0][k]; tot += red[1][k]; CC += red[2][k]; }
        float logZ = CC - __logf(hist[CRF_S - 1]) + __logf(ssum);
        atomicAdd(out, tot - logZ);
    }
}

extern "C" void kernel_launch(void* const* d_in, const int* in_sizes, int n_in,
                              void* d_out, int out_size)
{
    const float* logits = (const float*)d_in[0];
    const int*   tags   = (const int*)  d_in[1];
    // d_in[2] = mask: all ones per problem setup (unused)
    const float* trans  = (const float*)d_in[3];
    const float* st     = (const float*)d_in[4];
    const float* en     = (const float*)d_in[5];
    float* out = (float*)d_out;

    crf_zero<<<1, 32>>>(out);
    crf_forward_kernel<<<CRF_B, NTH>>>(logits, tags, trans, st, en, out);
}

// round 13
// speedup vs baseline: 1.0742x; 1.0742x over previous
#include <cuda_runtime.h>
#include <cuda_bf16.h>
#include <stdint.h>

// CRF log-likelihood: B=128, S=1024, T=256.
// Linear-domain forward recursion, one CTA per batch, 256 threads, thread=j.
//   q_t,j = (sum_i q_{t-1,i} E_ij) * exp(emit_t,j) / q_{t-1,0}
// E column in registers (128 bf16x2). q stored bf16 in smem (broadcast LDS).
// Split-phase named barrier (R10 champion): bar.arrive right after the q
// store; emit LDG + __expf prefetch execute in the arrive->wait window;
// bar.sync just before consuming q. ONE change vs R10: the normalizer
// q_{t-1,0} is taken from the MAC's own first chunk load (low bf16 of
// p4[0].x) instead of a separate LDS of hist[t-1] -- identical value,
// one less smem access on the post-sync critical path.
// hist telescope gives exact logZ with no MUFU on the critical path.

#define CRF_B 128
#define CRF_S 1024
#define CRF_T 256
#define NTH   256
#define BAR_CNT (2 * NTH)

__device__ __forceinline__ void bar_arrive1() {
    asm volatile("bar.arrive 1, %0;" :: "r"(BAR_CNT) : "memory");
}
__device__ __forceinline__ void bar_wait1() {
    asm volatile("bar.sync 1, %0;" :: "r"(BAR_CNT) : "memory");
}
__device__ __forceinline__ __nv_bfloat162 u2b(uint32_t u) {
    return *reinterpret_cast<__nv_bfloat162*>(&u);
}

__device__ __forceinline__ float warp_sum(float v) {
#pragma unroll
    for (int o = 16; o > 0; o >>= 1)
        v += __shfl_xor_sync(0xffffffffu, v, o);
    return v;
}

__global__ void crf_zero(float* out) {
    if (threadIdx.x == 0 && blockIdx.x == 0) out[0] = 0.0f;
}

__global__ void __launch_bounds__(NTH, 1) crf_forward_kernel(
    const float* __restrict__ logits,   // (B, S, T) f32
    const int*   __restrict__ tags,     // (B, S) i32
    const float* __restrict__ trans,    // (T, T) f32
    const float* __restrict__ start_t,  // (T,) f32
    const float* __restrict__ end_t,    // (T,) f32
    float* __restrict__ out)            // scalar
{
    __shared__ __align__(16) __nv_bfloat16 pbuf[2][CRF_T];
    __shared__ __align__(16) float hist[CRF_S];   // q_t,0 history
    __shared__ float red[3][8];

    const int j    = threadIdx.x;
    const int w    = j >> 5;
    const int lane = j & 31;
    const int b    = blockIdx.x;
    const float* lg = logits + (size_t)b * (CRF_S * CRF_T);

    // ---- E column j in registers: ereg[k] = (E[2k][j], E[2k+1][j]) ----
    __nv_bfloat162 ereg[128];
#pragma unroll
    for (int k = 0; k < 128; ++k) {
        float e0 = __expf(trans[(2 * k)     * CRF_T + j]);
        float e1 = __expf(trans[(2 * k + 1) * CRF_T + j]);
        ereg[k] = __floats2bfloat162_rn(e0, e1);
    }
    const float endv = end_t[j];

    // ---- t = 0: q_0 = exp(u_0) ----
    float u = start_t[j] + lg[j];
    float q0 = __expf(u);
    pbuf[0][j] = __float2bfloat16(q0);
    if (j == 0) hist[0] = __bfloat162float(__float2bfloat16(q0));
    __syncthreads();
    bar_arrive1();                        // open phase 0

    // emit pipeline: W_cur = exp(emit_t) ready one step ahead
    float e_raw = lg[(size_t)2 * CRF_T + j];          // emit for t = 2
    float W_cur = __expf(lg[(size_t)1 * CRF_T + j]);  // exp(emit) for t = 1
    __nv_bfloat162 q2 = __float2bfloat162_rn(q0);     // last q (bf16x2)

    // ---- forward scan, steps 1..S-1 ----
#pragma unroll 2
    for (int t = 1; t < CRF_S; ++t) {
        // arrive->wait window: independent prefetch work
        float W_next = __expf(e_raw);
        int tn = (t + 2 < CRF_S) ? (t + 2) : (CRF_S - 1);
        e_raw = lg[(size_t)tn * CRF_T + j];

        bar_wait1();                      // q_{t-1} now visible

        const uint4* p4 = reinterpret_cast<const uint4*>(pbuf[(t - 1) & 1]);
        __nv_bfloat162 z = __floats2bfloat162_rn(0.f, 0.f);
        __nv_bfloat162 a0 = z, a1 = z, a2 = z, a3 = z;
        __nv_bfloat162 a4 = z, a5 = z, a6 = z, a7 = z;

        // first chunk pair: reuse pw0.x for the normalizer (== hist[t-1])
        uint4 pw0 = p4[0];
        uint4 pw1 = p4[1];
        float qprev = __bfloat162float(__low2bfloat16(u2b(pw0.x)));
        float Wi = __fdividef(W_cur, qprev);          // hidden under MAC
        a0 = __hfma2(u2b(pw0.x), ereg[0], a0);
        a1 = __hfma2(u2b(pw0.y), ereg[1], a1);
        a2 = __hfma2(u2b(pw0.z), ereg[2], a2);
        a3 = __hfma2(u2b(pw0.w), ereg[3], a3);
        a4 = __hfma2(u2b(pw1.x), ereg[4], a4);
        a5 = __hfma2(u2b(pw1.y), ereg[5], a5);
        a6 = __hfma2(u2b(pw1.z), ereg[6], a6);
        a7 = __hfma2(u2b(pw1.w), ereg[7], a7);
#pragma unroll
        for (int c = 2; c < 32; c += 2) {
            uint4 pa = p4[c];
            uint4 pb = p4[c + 1];
            a0 = __hfma2(u2b(pa.x), ereg[4 * c + 0], a0);
            a1 = __hfma2(u2b(pa.y), ereg[4 * c + 1], a1);
            a2 = __hfma2(u2b(pa.z), ereg[4 * c + 2], a2);
            a3 = __hfma2(u2b(pa.w), ereg[4 * c + 3], a3);
            a4 = __hfma2(u2b(pb.x), ereg[4 * c + 4], a4);
            a5 = __hfma2(u2b(pb.y), ereg[4 * c + 5], a5);
            a6 = __hfma2(u2b(pb.z), ereg[4 * c + 6], a6);
            a7 = __hfma2(u2b(pb.w), ereg[4 * c + 7], a7);
        }
        __nv_bfloat162 Wi2 = __floats2bfloat162_rn(Wi, Wi);
        __nv_bfloat162 b0 = __hadd2(a0, a1);
        __nv_bfloat162 b1 = __hadd2(a2, a3);
        __nv_bfloat162 b2 = __hadd2(a4, a5);
        __nv_bfloat162 b3 = __hadd2(a6, a7);
        __nv_bfloat162 s  = __hadd2(__hadd2(b0, b1), __hadd2(b2, b3));
        __nv_bfloat162 tot = __hadd2(s, __lowhigh2highlow(s));
        q2 = __hmul2(tot, Wi2);                       // q_t,j (bf16x2)

        pbuf[t & 1][j] = __low2bfloat16(q2);          // STS.16
        if (j == 0) hist[t] = __bfloat162float(__low2bfloat16(q2));
        bar_arrive1();                                // open next phase

        W_cur = W_next;
    }
    bar_wait1();                                      // close final phase

    // ---- logZ pieces ----
    float qf = __bfloat162float(__low2bfloat16(q2));  // q_{S-1,j}
    // (a) sum_j q_{S-1,j} * exp(end_j)
    float ws = warp_sum(qf * __expf(endv));
    if (lane == 0) red[0][w] = ws;

    // (b) CC = sum_t log hist[t]  (4 entries per thread)
    float cc = __logf(hist[j]) + __logf(hist[j + 256])
             + __logf(hist[j + 512]) + __logf(hist[j + 768]);
    float wcc = warp_sum(cc);
    if (lane == 0) red[2][w] = wcc;

    // (c) joint score (numerator); mask is all-ones for this problem
    const int* tg = tags + b * CRF_S;
    float num = 0.f;
#pragma unroll
    for (int t = j; t < CRF_S; t += NTH) {
        int tt = tg[t];
        num += lg[(size_t)t * CRF_T + tt];
        if (t + 1 < CRF_S) num += trans[tt * CRF_T + tg[t + 1]];
    }
    if (j == 0) num += start_t[tg[0]] + end_t[tg[CRF_S - 1]];
    float wsn = warp_sum(num);
    if (lane == 0) red[1][w] = wsn;
    __syncthreads();

    if (j == 0) {
        float ssum = 0.f, tot = 0.f, CC = 0.f;
#pragma unroll
        for (int k = 0; k < 8; ++k) { ssum += red[0][k]; tot += red[1][k]; CC += red[2][k]; }
        float logZ = CC - __logf(hist[CRF_S - 1]) + __logf(ssum);
        atomicAdd(out, tot - logZ);
    }
}

extern "C" void kernel_launch(void* const* d_in, const int* in_sizes, int n_in,
                              void* d_out, int out_size)
{
    const float* logits = (const float*)d_in[0];
    const int*   tags   = (const int*)  d_in[1];
    // d_in[2] = mask: all ones per problem setup (unused)
    const float* trans  = (const float*)d_in[3];
    const float* st     = (const float*)d_in[4];
    const float* en     = (const float*)d_in[5];
    float* out = (float*)d_out;

    crf_zero<<<1, 32>>>(out);
    crf_forward_kernel<<<CRF_B, NTH>>>(logits, tags, trans, st, en, out);
}

// round 14
// speedup vs baseline: 1.2215x; 1.1372x over previous
#include <cuda_runtime.h>
#include <cuda_bf16.h>
#include <stdint.h>

// CRF log-likelihood: B=128, S=1024, T=256.
// Linear-domain forward recursion, one CTA per batch, 256 threads, thread=j.
//   q_t,j = (sum_i q_{t-1,i} E_ij) * exp(emit_t,j) / q_{t-1,0}
// E column in registers (128 bf16x2). q stored bf16 in smem (broadcast LDS).
// Split-phase named barrier: bar.arrive right after the q store; emit
// pipeline work runs in the arrive->wait window; bar.sync just before
// consuming q. EMIT PIPELINE IS 2 LOADS DEEP: raw logits for t+2 AND t+3
// are in flight, giving every LDG ~2 steps (>1800 cy) before its __expf --
// covers NAT DRAM latency so no warp stalls ahead of the barrier.
// Normalizer q_{t-1,0} comes from the MAC's own first chunk load.
// hist telescope gives exact logZ with no MUFU on the critical path.

#define CRF_B 128
#define CRF_S 1024
#define CRF_T 256
#define NTH   256
#define BAR_CNT (2 * NTH)

__device__ __forceinline__ void bar_arrive1() {
    asm volatile("bar.arrive 1, %0;" :: "r"(BAR_CNT) : "memory");
}
__device__ __forceinline__ void bar_wait1() {
    asm volatile("bar.sync 1, %0;" :: "r"(BAR_CNT) : "memory");
}
__device__ __forceinline__ __nv_bfloat162 u2b(uint32_t u) {
    return *reinterpret_cast<__nv_bfloat162*>(&u);
}

__device__ __forceinline__ float warp_sum(float v) {
#pragma unroll
    for (int o = 16; o > 0; o >>= 1)
        v += __shfl_xor_sync(0xffffffffu, v, o);
    return v;
}

__global__ void crf_zero(float* out) {
    if (threadIdx.x == 0 && blockIdx.x == 0) out[0] = 0.0f;
}

__global__ void __launch_bounds__(NTH, 1) crf_forward_kernel(
    const float* __restrict__ logits,   // (B, S, T) f32
    const int*   __restrict__ tags,     // (B, S) i32
    const float* __restrict__ trans,    // (T, T) f32
    const float* __restrict__ start_t,  // (T,) f32
    const float* __restrict__ end_t,    // (T,) f32
    float* __restrict__ out)            // scalar
{
    __shared__ __align__(16) __nv_bfloat16 pbuf[2][CRF_T];
    __shared__ __align__(16) float hist[CRF_S];   // q_t,0 history
    __shared__ float red[3][8];

    const int j    = threadIdx.x;
    const int w    = j >> 5;
    const int lane = j & 31;
    const int b    = blockIdx.x;
    const float* lg = logits + (size_t)b * (CRF_S * CRF_T);

    // ---- E column j in registers: ereg[k] = (E[2k][j], E[2k+1][j]) ----
    __nv_bfloat162 ereg[128];
#pragma unroll
    for (int k = 0; k < 128; ++k) {
        float e0 = __expf(trans[(2 * k)     * CRF_T + j]);
        float e1 = __expf(trans[(2 * k + 1) * CRF_T + j]);
        ereg[k] = __floats2bfloat162_rn(e0, e1);
    }
    const float endv = end_t[j];

    // ---- t = 0: q_0 = exp(u_0) ----
    float u = start_t[j] + lg[j];
    float q0 = __expf(u);
    pbuf[0][j] = __float2bfloat16(q0);
    if (j == 0) hist[0] = __bfloat162float(__float2bfloat16(q0));
    __syncthreads();
    bar_arrive1();                        // open phase 0

    // emit pipeline, 2 raw loads deep:
    //   W_cur  = exp(emit_t)      (consumed this step)
    //   W_next = exp(emit_{t+1})
    //   e_raw_a = raw emit_{t+2},  e_raw_b = raw emit_{t+3}
    float W_cur   = __expf(lg[(size_t)1 * CRF_T + j]);
    float W_next  = __expf(lg[(size_t)2 * CRF_T + j]);
    float e_raw_a = lg[(size_t)3 * CRF_T + j];
    float e_raw_b = lg[(size_t)4 * CRF_T + j];
    __nv_bfloat162 q2 = __float2bfloat162_rn(q0);     // last q (bf16x2)

    // ---- forward scan, steps 1..S-1 ----
#pragma unroll 2
    for (int t = 1; t < CRF_S; ++t) {
        // arrive->wait window: rotate the emit pipeline (all off-path)
        float W_new = __expf(e_raw_a);
        e_raw_a = e_raw_b;
        int tn = (t + 5 < CRF_S) ? (t + 5) : (CRF_S - 1);
        e_raw_b = lg[(size_t)tn * CRF_T + j];

        bar_wait1();                      // q_{t-1} now visible

        const uint4* p4 = reinterpret_cast<const uint4*>(pbuf[(t - 1) & 1]);
        __nv_bfloat162 z = __floats2bfloat162_rn(0.f, 0.f);
        __nv_bfloat162 a0 = z, a1 = z, a2 = z, a3 = z;
        __nv_bfloat162 a4 = z, a5 = z, a6 = z, a7 = z;

        // first chunk pair: reuse pw0.x for the normalizer (== hist[t-1])
        uint4 pw0 = p4[0];
        uint4 pw1 = p4[1];
        float qprev = __bfloat162float(__low2bfloat16(u2b(pw0.x)));
        float Wi = __fdividef(W_cur, qprev);          // hidden under MAC
        a0 = __hfma2(u2b(pw0.x), ereg[0], a0);
        a1 = __hfma2(u2b(pw0.y), ereg[1], a1);
        a2 = __hfma2(u2b(pw0.z), ereg[2], a2);
        a3 = __hfma2(u2b(pw0.w), ereg[3], a3);
        a4 = __hfma2(u2b(pw1.x), ereg[4], a4);
        a5 = __hfma2(u2b(pw1.y), ereg[5], a5);
        a6 = __hfma2(u2b(pw1.z), ereg[6], a6);
        a7 = __hfma2(u2b(pw1.w), ereg[7], a7);
#pragma unroll
        for (int c = 2; c < 32; c += 2) {
            uint4 pa = p4[c];
            uint4 pb = p4[c + 1];
            a0 = __hfma2(u2b(pa.x), ereg[4 * c + 0], a0);
            a1 = __hfma2(u2b(pa.y), ereg[4 * c + 1], a1);
            a2 = __hfma2(u2b(pa.z), ereg[4 * c + 2], a2);
            a3 = __hfma2(u2b(pa.w), ereg[4 * c + 3], a3);
            a4 = __hfma2(u2b(pb.x), ereg[4 * c + 4], a4);
            a5 = __hfma2(u2b(pb.y), ereg[4 * c + 5], a5);
            a6 = __hfma2(u2b(pb.z), ereg[4 * c + 6], a6);
            a7 = __hfma2(u2b(pb.w), ereg[4 * c + 7], a7);
        }
        __nv_bfloat162 Wi2 = __floats2bfloat162_rn(Wi, Wi);
        __nv_bfloat162 b0 = __hadd2(a0, a1);
        __nv_bfloat162 b1 = __hadd2(a2, a3);
        __nv_bfloat162 b2 = __hadd2(a4, a5);
        __nv_bfloat162 b3 = __hadd2(a6, a7);
        __nv_bfloat162 s  = __hadd2(__hadd2(b0, b1), __hadd2(b2, b3));
        __nv_bfloat162 tot = __hadd2(s, __lowhigh2highlow(s));
        q2 = __hmul2(tot, Wi2);                       // q_t,j (bf16x2)

        pbuf[t & 1][j] = __low2bfloat16(q2);          // STS.16
        if (j == 0) hist[t] = __bfloat162float(__low2bfloat16(q2));
        bar_arrive1();                                // open next phase

        W_cur = W_next;
        W_next = W_new;
    }
    bar_wait1();                                      // close final phase

    // ---- logZ pieces ----
    float qf = __bfloat162float(__low2bfloat16(q2));  // q_{S-1,j}
    // (a) sum_j q_{S-1,j} * exp(end_j)
    float ws = warp_sum(qf * __expf(endv));
    if (lane == 0) red[0][w] = ws;

    // (b) CC = sum_t log hist[t]  (4 entries per thread)
    float cc = __logf(hist[j]) + __logf(hist[j + 256])
             + __logf(hist[j + 512]) + __logf(hist[j + 768]);
    float wcc = warp_sum(cc);
    if (lane == 0) red[2][w] = wcc;

    // (c) joint score (numerator); mask is all-ones for this problem
    const int* tg = tags + b * CRF_S;
    float num = 0.f;
#pragma unroll
    for (int t = j; t < CRF_S; t += NTH) {
        int tt = tg[t];
        num += lg[(size_t)t * CRF_T + tt];
        if (t + 1 < CRF_S) num += trans[tt * CRF_T + tg[t + 1]];
    }
    if (j == 0) num += start_t[tg[0]] + end_t[tg[CRF_S - 1]];
    float wsn = warp_sum(num);
    if (lane == 0) red[1][w] = wsn;
    __syncthreads();

    if (j == 0) {
        float ssum = 0.f, tot = 0.f, CC = 0.f;
#pragma unroll
        for (int k = 0; k < 8; ++k) { ssum += red[0][k]; tot += red[1][k]; CC += red[2][k]; }
        float logZ = CC - __logf(hist[CRF_S - 1]) + __logf(ssum);
        atomicAdd(out, tot - logZ);
    }
}

extern "C" void kernel_launch(void* const* d_in, const int* in_sizes, int n_in,
                              void* d_out, int out_size)
{
    const float* logits = (const float*)d_in[0];
    const int*   tags   = (const int*)  d_in[1];
    // d_in[2] = mask: all ones per problem setup (unused)
    const float* trans  = (const float*)d_in[3];
    const float* st     = (const float*)d_in[4];
    const float* en     = (const float*)d_in[5];
    float* out = (float*)d_out;

    crf_zero<<<1, 32>>>(out);
    crf_forward_kernel<<<CRF_B, NTH>>>(logits, tags, trans, st, en, out);
}